// round 9
// baseline (speedup 1.0000x reference)
#include <cuda_runtime.h>
#include <cstdint>

#define HW_   56
#define C_    128
#define F_    128
#define B_    32
#define PIX_  (HW_*HW_)
#define XHW   58                 // padded spatial
#define STAGE 32768              // A 16KB + B 16KB
#define NST   3
#define DYN   (NST*STAGE + 1024)

// device scratch (static globals = allowed)
__device__ float g_xh[(size_t)B_ * XHW * XHW * C_];  // [b][hp][wp][cperm]
__device__ float g_wt[9 * 4 * 128 * 32];             // [tap][cc][f][kperm]

__device__ __forceinline__ uint32_t smem_u32(const void* p) {
    uint32_t a;
    asm("{ .reg .u64 t; cvta.to.shared.u64 t, %1; cvt.u32.u64 %0, t; }" : "=r"(a) : "l"(p));
    return a;
}
__device__ __forceinline__ void mma_tf32(float d[4], const uint32_t a[4], const uint32_t b[2]) {
    asm volatile(
        "mma.sync.aligned.m16n8k8.row.col.f32.tf32.tf32.f32 "
        "{%0,%1,%2,%3}, {%4,%5,%6,%7}, {%8,%9}, {%0,%1,%2,%3};\n"
        : "+f"(d[0]), "+f"(d[1]), "+f"(d[2]), "+f"(d[3])
        : "r"(a[0]), "r"(a[1]), "r"(a[2]), "r"(a[3]), "r"(b[0]), "r"(b[1]));
}
#define CP_CG(d, s) asm volatile("cp.async.cg.shared.global [%0], [%1], 16;" :: "r"(d), "l"(s))
#define CP_CA(d, s) asm volatile("cp.async.ca.shared.global [%0], [%1], 16;" :: "r"(d), "l"(s))
#define CP_COMMIT() asm volatile("cp.async.commit_group;" ::: "memory")
#define LDS64(r0, r1, a) asm volatile("ld.shared.v2.b32 {%0,%1}, [%2];" : "=r"(r0), "=r"(r1) : "r"(a))

// channel pair-permute within 8-block (k-pair layout for conflict-free LDS.64)
__device__ __host__ __forceinline__ int permC(int c) {
    return (c & ~7) | ((c & 3) << 1) | ((c >> 2) & 1);
}
// inverse: q -> c with permC(c) = q
__device__ __forceinline__ int invPermC(int q) {
    return (q & ~7) | ((q & 7) >> 1) | ((q & 1) << 2);
}

// ---------- prologue 1: x NCHW -> zero-padded NHWC (channel-permuted) ----------
__global__ __launch_bounds__(256) void k_transpose_x(const float* __restrict__ x) {
    __shared__ float s[HW_ * 130];
    const int hp = blockIdx.x, bb = blockIdx.y, tid = threadIdx.x;
    float* dst = g_xh + ((size_t)(bb * XHW + hp) * XHW) * C_;
    if (hp == 0 || hp == XHW - 1) {
        float4 z = make_float4(0.f, 0.f, 0.f, 0.f);
        for (int i = tid; i < XHW * 32; i += 256) ((float4*)dst)[i] = z;
        return;
    }
    const float* src = x + ((size_t)bb * C_) * PIX_ + (hp - 1) * HW_;
    // phase 1: vectorized loads (56 = 14 float4 per channel row)
    for (int i = tid; i < C_ * 14; i += 256) {
        int c = i / 14, w4 = i - c * 14;
        float4 v = *(const float4*)(src + (size_t)c * PIX_ + w4 * 4);
        float* sc = s + (w4 * 4) * 130 + c;
        sc[0]   = v.x;
        sc[130] = v.y;
        sc[260] = v.z;
        sc[390] = v.w;
    }
    __syncthreads();
    // phase 2: permuted-channel gather, float4 global stores
    for (int o = tid; o < XHW * 32; o += 256) {
        int wp = o >> 5, q4 = (o & 31) << 2;
        float4 v = make_float4(0.f, 0.f, 0.f, 0.f);
        if (wp != 0 && wp != XHW - 1) {
            const float* sr = s + (wp - 1) * 130;
            v.x = sr[invPermC(q4 + 0)];
            v.y = sr[invPermC(q4 + 1)];
            v.z = sr[invPermC(q4 + 2)];
            v.w = sr[invPermC(q4 + 3)];
        }
        ((float4*)dst)[o] = v;
    }
}

// ---------- prologue 2: W[(c*9+tap)][f] -> g_wt[tap][cc][f][kperm] ----------
__global__ __launch_bounds__(256) void k_transpose_w(const float* __restrict__ Wg) {
    int i = blockIdx.x * 256 + threadIdx.x;
    if (i < 9 * 4 * 128 * 32) {
        int t  = i / 16384;
        int r  = i - t * 16384;
        int cc = r >> 12;
        int r2 = r & 4095;
        int n  = r2 >> 5;
        int j  = r2 & 31;
        int c  = cc * 32 + ((j >> 3) << 3) + ((j >> 1) & 3) + ((j & 1) << 2);
        g_wt[i] = Wg[(c * 9 + t) * F_ + n];
    }
}

// ---------- main: 8 warps x (32x64) tiles, 16 warps/SM, depth-2 pipeline ----------
__global__ __launch_bounds__(256, 2)
void k_conv_main(const float* __restrict__ Di, float* __restrict__ out) {
    extern __shared__ float dynsmem[];
    uint32_t dbase = smem_u32(dynsmem);
    dbase = (dbase + 1023u) & ~1023u;

    const int tid   = threadIdx.x;
    const int lane  = tid & 31;
    const int warp  = tid >> 5;
    const int warpM = warp >> 1;   // 0..3 -> 32 rows each
    const int warpN = warp & 1;    // 0..1 -> 64 cols each
    const int T     = blockIdx.x;  // pixels [T*128, T*128+128)

    float thr[8][2];
    #pragma unroll
    for (int nt = 0; nt < 8; nt++) {
        int f = warpN * 64 + nt * 8 + 2 * (lane & 3);
        thr[nt][0] = 1.0f - Di[f];
        thr[nt][1] = 1.0f - Di[f + 1];
    }

    float acc[2][8][4];
    #pragma unroll
    for (int mt = 0; mt < 2; mt++)
        #pragma unroll
        for (int nt = 0; nt < 8; nt++)
            #pragma unroll
            for (int r = 0; r < 4; r++) acc[mt][nt][r] = 0.0f;

    // ---- cp.async tables: 4 A + 4 B 16B-copies per thread (256 thr) ----
    int srcA[4]; uint32_t dstA[4], dstB[4];
    #pragma unroll
    for (int i = 0; i < 4; i++) {
        int idx = tid + 256 * i;        // 0..1023
        int m = idx >> 3, g = idx & 7;
        int p = T * 128 + m;
        int bb = p / PIX_;
        int r  = p - bb * PIX_;
        int h  = r / HW_;
        int w  = r - h * HW_;
        srcA[i] = ((bb * XHW + h) * XHW + w) * 512 + g * 16;
        dstA[i] = m * 128 + ((g ^ (m & 7)) << 4);
        dstB[i] = 16384 + dstA[i];
    }
    const char* xh = (const char*)g_xh;
    const char* wt = (const char*)g_wt;

    // fragment geometry (swizzled LDS.64)
    const int cA = lane & 3;
    const int x2 = 2 * ((lane >> 2) & 7);
    int okk[4];
    #pragma unroll
    for (int kk = 0; kk < 4; kk++) okk[kk] = ((kk * 4 + cA) ^ x2) << 3;
    uint32_t ab[2][2], bbf[8];
    #pragma unroll
    for (int mt = 0; mt < 2; mt++) {
        int r0 = warpM * 32 + mt * 16 + (lane >> 2);
        ab[mt][0] = r0 * 128;
        ab[mt][1] = (r0 + 8) * 128;
    }
    #pragma unroll
    for (int nt = 0; nt < 8; nt++) {
        int n = warpN * 64 + nt * 8 + (lane >> 2);
        bbf[nt] = 16384 + n * 128;
    }

    auto issue = [&](int s, uint32_t sb) {
        int tap = s >> 2, cc = s & 3;
        int dh = tap / 3, dw = tap - dh * 3;
        int aadd = (dh * XHW + dw) * 512 + cc * 128;
        long badd = (long)s * 16384;
        #pragma unroll
        for (int i = 0; i < 4; i++) CP_CG(sb + dstA[i], xh + srcA[i] + aadd);
        #pragma unroll
        for (int i = 0; i < 4; i++) CP_CA(sb + dstB[i], wt + (long)(tid + 256 * i) * 16 + badd);
        CP_COMMIT();
    };

    // ---- depth-2 cp.async pipeline, one barrier per step ----
    uint32_t sb0 = dbase, sb1 = dbase + STAGE, sb2 = dbase + 2 * STAGE;
    issue(0, sb0);
    issue(1, sb1);
    #pragma unroll 1
    for (int s = 0; s < 36; s++) {
        if (s < 35) { asm volatile("cp.async.wait_group 1;" ::: "memory"); }
        else        { asm volatile("cp.async.wait_group 0;" ::: "memory"); }
        __syncthreads();
        if (s < 34) issue(s + 2, sb2);

        #pragma unroll
        for (int kk = 0; kk < 4; kk++) {
            const int o = okk[kk];
            uint32_t a[2][4];
            #pragma unroll
            for (int mt = 0; mt < 2; mt++) {
                LDS64(a[mt][0], a[mt][2], sb0 + ab[mt][0] + o);
                LDS64(a[mt][1], a[mt][3], sb0 + ab[mt][1] + o);
            }
            uint32_t bf[8][2];
            #pragma unroll
            for (int nt = 0; nt < 8; nt++)
                LDS64(bf[nt][0], bf[nt][1], sb0 + bbf[nt] + o);
            #pragma unroll
            for (int mt = 0; mt < 2; mt++)
                #pragma unroll
                for (int nt = 0; nt < 8; nt++)
                    mma_tf32(acc[mt][nt], a[mt], bf[nt]);
        }
        uint32_t t0 = sb0; sb0 = sb1; sb1 = sb2; sb2 = t0;   // rotate stages
    }

    // ---- epilogue: ti = min(y + 1 - Di[f], 1), NHWC float2 stores ----
    #pragma unroll
    for (int mt = 0; mt < 2; mt++) {
        #pragma unroll
        for (int half = 0; half < 2; half++) {
            int m = warpM * 32 + mt * 16 + half * 8 + (lane >> 2);
            int p = T * 128 + m;
            int bb = p / PIX_;
            int r  = p - bb * PIX_;
            float* op = out + ((size_t)bb * PIX_ + r) * F_;
            #pragma unroll
            for (int nt = 0; nt < 8; nt++) {
                int f = warpN * 64 + nt * 8 + 2 * (lane & 3);
                float2 vv;
                vv.x = fminf(acc[mt][nt][2 * half + 0] + thr[nt][0], 1.0f);
                vv.y = fminf(acc[mt][nt][2 * half + 1] + thr[nt][1], 1.0f);
                *(float2*)(op + f) = vv;
            }
        }
    }
}

extern "C" void kernel_launch(void* const* d_in, const int* in_sizes, int n_in,
                              void* d_out, int out_size) {
    (void)in_sizes; (void)n_in; (void)out_size;
    const float* x  = (const float*)d_in[0];
    const float* Wg = (const float*)d_in[1];
    const float* Di = (const float*)d_in[2];
    float* out = (float*)d_out;

    cudaFuncSetAttribute(k_conv_main, cudaFuncAttributeMaxDynamicSharedMemorySize, DYN);

    dim3 gx(XHW, B_);
    k_transpose_x<<<gx, 256>>>(x);
    k_transpose_w<<<(9 * 4 * 128 * 32 + 255) / 256, 256>>>(Wg);

    k_conv_main<<<784, 256, DYN>>>(Di, out);
}

// round 10
// speedup vs baseline: 2.5054x; 2.5054x over previous
#include <cuda_runtime.h>
#include <cuda_fp16.h>
#include <cstdint>

#define HW_   56
#define C_    128
#define F_    128
#define B_    32
#define PIX_  (HW_*HW_)
#define XHW   58                 // padded spatial
#define STAGE 32768              // A 16KB + B 16KB (halves, K=64 per step)
#define NST   3
#define DYN   (NST*STAGE + 1024)

// device scratch (static globals = allowed)
__device__ __half g_xh[(size_t)B_ * XHW * XHW * C_];  // [b][hp][wp][c] fp16, zero halo
__device__ __half g_wt[18 * 128 * 64];                // [tap*2+hc][f][c(64)] fp16

__device__ __forceinline__ uint32_t smem_u32(const void* p) {
    uint32_t a;
    asm("{ .reg .u64 t; cvta.to.shared.u64 t, %1; cvt.u32.u64 %0, t; }" : "=r"(a) : "l"(p));
    return a;
}
__device__ __forceinline__ void mma_f16(float d[4], const uint32_t a[4], const uint32_t b[2]) {
    asm volatile(
        "mma.sync.aligned.m16n8k16.row.col.f32.f16.f16.f32 "
        "{%0,%1,%2,%3}, {%4,%5,%6,%7}, {%8,%9}, {%0,%1,%2,%3};\n"
        : "+f"(d[0]), "+f"(d[1]), "+f"(d[2]), "+f"(d[3])
        : "r"(a[0]), "r"(a[1]), "r"(a[2]), "r"(a[3]), "r"(b[0]), "r"(b[1]));
}
#define LDSM4(r0, r1, r2, r3, a) \
    asm volatile("ldmatrix.sync.aligned.m8n8.x4.shared.b16 {%0,%1,%2,%3}, [%4];" \
                 : "=r"(r0), "=r"(r1), "=r"(r2), "=r"(r3) : "r"(a))
#define CP_CG(d, s) asm volatile("cp.async.cg.shared.global [%0], [%1], 16;" :: "r"(d), "l"(s))
#define CP_CA(d, s) asm volatile("cp.async.ca.shared.global [%0], [%1], 16;" :: "r"(d), "l"(s))
#define CP_COMMIT() asm volatile("cp.async.commit_group;" ::: "memory")

// ---------- prologue 1: x NCHW fp32 -> zero-padded NHWC fp16 ----------
__global__ __launch_bounds__(256) void k_transpose_x(const float* __restrict__ x) {
    __shared__ float s[HW_ * 130];
    const int hp = blockIdx.x, bb = blockIdx.y, tid = threadIdx.x;
    __half* dst = g_xh + ((size_t)(bb * XHW + hp) * XHW) * C_;
    if (hp == 0 || hp == XHW - 1) {
        uint4 z = make_uint4(0, 0, 0, 0);
        for (int i = tid; i < XHW * 16; i += 256) ((uint4*)dst)[i] = z;  // 8 halves each
        return;
    }
    const float* src = x + ((size_t)bb * C_) * PIX_ + (hp - 1) * HW_;
    for (int i = tid; i < C_ * 14; i += 256) {          // 14 float4 per channel row
        int c = i / 14, w4 = i - c * 14;
        float4 v = *(const float4*)(src + (size_t)c * PIX_ + w4 * 4);
        float* sc = s + (w4 * 4) * 130 + c;
        sc[0]   = v.x;
        sc[130] = v.y;
        sc[260] = v.z;
        sc[390] = v.w;
    }
    __syncthreads();
    for (int o = tid; o < XHW * 32; o += 256) {         // 4 channels -> uint2 (4 halves)
        int wp = o >> 5, c4 = (o & 31) << 2;
        uint2 hv = make_uint2(0u, 0u);
        if (wp != 0 && wp != XHW - 1) {
            const float* sr = s + (wp - 1) * 130;
            __half2 h0 = __floats2half2_rn(sr[c4 + 0], sr[c4 + 1]);
            __half2 h1 = __floats2half2_rn(sr[c4 + 2], sr[c4 + 3]);
            hv.x = *(uint32_t*)&h0;
            hv.y = *(uint32_t*)&h1;
        }
        ((uint2*)dst)[o] = hv;
    }
}

// ---------- prologue 2: W[(c*9+tap)][f] fp32 -> g_wt[tap*2+hc][f][cl] fp16 ----------
__global__ __launch_bounds__(256) void k_transpose_w(const float* __restrict__ Wg) {
    int i = blockIdx.x * 256 + threadIdx.x;
    if (i < 18 * 128 * 64) {
        int t2 = i / 8192;               // tap*2 + hc
        int r  = i - t2 * 8192;
        int f  = r >> 6;
        int cl = r & 63;
        int tap = t2 >> 1;
        int c   = ((t2 & 1) << 6) + cl;
        g_wt[i] = __float2half_rn(Wg[(c * 9 + tap) * F_ + f]);
    }
}

// ---------- main: fp16 mma.m16n8k16 + ldmatrix, 4 warps x (64x64), K=64 steps ----------
__global__ __launch_bounds__(128, 2)
void k_conv_main(const float* __restrict__ Di, float* __restrict__ out) {
    extern __shared__ float dynsmem[];
    uint32_t dbase = smem_u32(dynsmem);
    dbase = (dbase + 1023u) & ~1023u;

    const int tid   = threadIdx.x;
    const int lane  = tid & 31;
    const int warp  = tid >> 5;
    const int warpM = warp >> 1;   // 0..1 -> 64 rows
    const int warpN = warp & 1;    // 0..1 -> 64 cols
    const int T     = blockIdx.x;  // pixels [T*128, T*128+128)

    float thr[8][2];
    #pragma unroll
    for (int nt = 0; nt < 8; nt++) {
        int f = warpN * 64 + nt * 8 + 2 * (lane & 3);
        thr[nt][0] = 1.0f - Di[f];
        thr[nt][1] = 1.0f - Di[f + 1];
    }

    float acc[4][8][4];
    #pragma unroll
    for (int mt = 0; mt < 4; mt++)
        #pragma unroll
        for (int nt = 0; nt < 8; nt++)
            #pragma unroll
            for (int r = 0; r < 4; r++) acc[mt][nt][r] = 0.0f;

    // ---- cp.async tables: 8 A + 8 B 16B-copies per thread (128 thr) ----
    // A stage: 128 pixel-rows x 128B (64 halves); B stage: 128 f-rows x 128B
    int srcA[8]; uint32_t dstA[8], dstB[8];
    #pragma unroll
    for (int i = 0; i < 8; i++) {
        int idx = tid + 128 * i;        // 0..1023
        int m = idx >> 3, g = idx & 7;
        int p = T * 128 + m;
        int bb = p / PIX_;
        int r  = p - bb * PIX_;
        int h  = r / HW_;
        int w  = r - h * HW_;
        srcA[i] = ((bb * XHW + h) * XHW + w) * 256 + g * 16;   // 256B per pixel (128 halves)
        dstA[i] = m * 128 + ((g ^ (m & 7)) << 4);
        dstB[i] = 16384 + dstA[i];
    }
    const char* xh = (const char*)g_xh;
    const char* wt = (const char*)g_wt;

    // ---- ldmatrix lane geometry ----
    const int l7 = lane & 7;
    const int rA = l7 + ((lane >> 3) & 1) * 8;   // A: M0/M2 rows, M1/M3 rows+8 pattern
    const int gA = lane >> 4;                     // A: k-granule select
    const int rB = l7 + ((lane >> 4) & 1) * 8;   // B: lanes 16-31 -> n+8
    const int gB = (lane >> 3) & 1;              // B: k-granule select
    // swizzled granule offsets per k16-slice ks: col16 = (2*ks + gsel) ^ l7
    uint32_t offA[4], offB[4];
    #pragma unroll
    for (int ks = 0; ks < 4; ks++) {
        offA[ks] = (((2 * ks + gA) ^ l7) << 4);
        offB[ks] = (((2 * ks + gB) ^ l7) << 4);
    }
    uint32_t abase[4], bbase[4];
    #pragma unroll
    for (int mt = 0; mt < 4; mt++) abase[mt] = (warpM * 64 + mt * 16 + rA) * 128;
    #pragma unroll
    for (int np = 0; np < 4; np++) bbase[np] = 16384 + (warpN * 64 + np * 16 + rB) * 128;

    auto issue = [&](int s, uint32_t sb) {
        int tap = s >> 1, hc = s & 1;
        int dh = tap / 3, dw = tap - dh * 3;
        int aadd = (dh * XHW + dw) * 256 + hc * 128;
        long badd = (long)s * 16384;
        #pragma unroll
        for (int i = 0; i < 8; i++) CP_CG(sb + dstA[i], xh + srcA[i] + aadd);
        #pragma unroll
        for (int i = 0; i < 8; i++) CP_CA(sb + dstB[i], wt + (long)(tid + 128 * i) * 16 + badd);
        CP_COMMIT();
    };

    // ---- depth-2 cp.async pipeline: 18 steps of K=64 ----
    uint32_t sb0 = dbase, sb1 = dbase + STAGE, sb2 = dbase + 2 * STAGE;
    issue(0, sb0);
    issue(1, sb1);
    #pragma unroll 1
    for (int s = 0; s < 18; s++) {
        if (s < 17) { asm volatile("cp.async.wait_group 1;" ::: "memory"); }
        else        { asm volatile("cp.async.wait_group 0;" ::: "memory"); }
        __syncthreads();
        if (s < 16) issue(s + 2, sb2);

        #pragma unroll
        for (int ks = 0; ks < 4; ks++) {
            uint32_t a[4][4];
            #pragma unroll
            for (int mt = 0; mt < 4; mt++)
                LDSM4(a[mt][0], a[mt][1], a[mt][2], a[mt][3], sb0 + abase[mt] + offA[ks]);
            uint32_t bf[4][4];   // np covers nt=2np (regs 0,1) and nt=2np+1 (regs 2,3)
            #pragma unroll
            for (int np = 0; np < 4; np++)
                LDSM4(bf[np][0], bf[np][1], bf[np][2], bf[np][3], sb0 + bbase[np] + offB[ks]);
            #pragma unroll
            for (int mt = 0; mt < 4; mt++)
                #pragma unroll
                for (int np = 0; np < 4; np++) {
                    mma_f16(acc[mt][2 * np + 0], a[mt], &bf[np][0]);
                    mma_f16(acc[mt][2 * np + 1], a[mt], &bf[np][2]);
                }
        }
        uint32_t t0 = sb0; sb0 = sb1; sb1 = sb2; sb2 = t0;   // rotate stages
    }

    // ---- epilogue: ti = min(y + 1 - Di[f], 1), NHWC float2 stores ----
    #pragma unroll
    for (int mt = 0; mt < 4; mt++) {
        #pragma unroll
        for (int half = 0; half < 2; half++) {
            int m = warpM * 64 + mt * 16 + half * 8 + (lane >> 2);
            int p = T * 128 + m;
            int bb = p / PIX_;
            int r  = p - bb * PIX_;
            float* op = out + ((size_t)bb * PIX_ + r) * F_;
            #pragma unroll
            for (int nt = 0; nt < 8; nt++) {
                int f = warpN * 64 + nt * 8 + 2 * (lane & 3);
                float2 vv;
                vv.x = fminf(acc[mt][nt][2 * half + 0] + thr[nt][0], 1.0f);
                vv.y = fminf(acc[mt][nt][2 * half + 1] + thr[nt][1], 1.0f);
                *(float2*)(op + f) = vv;
            }
        }
    }
}

extern "C" void kernel_launch(void* const* d_in, const int* in_sizes, int n_in,
                              void* d_out, int out_size) {
    (void)in_sizes; (void)n_in; (void)out_size;
    const float* x  = (const float*)d_in[0];
    const float* Wg = (const float*)d_in[1];
    const float* Di = (const float*)d_in[2];
    float* out = (float*)d_out;

    cudaFuncSetAttribute(k_conv_main, cudaFuncAttributeMaxDynamicSharedMemorySize, DYN);

    dim3 gx(XHW, B_);
    k_transpose_x<<<gx, 256>>>(x);
    k_transpose_w<<<(18 * 128 * 64 + 255) / 256, 256>>>(Wg);

    k_conv_main<<<784, 128, DYN>>>(Di, out);
}